// round 16
// baseline (speedup 1.0000x reference)
#include <cuda_runtime.h>
#include <cuda_fp16.h>
#include <cstdint>

// ============================================================================
// Problem constants
// ============================================================================
#define B_ROWS 4096
#define D_DIM  1024
#define TEMP   0.2f

// GEMM tiling: sim[4096,4096] = z_j (M side) @ z_i^T (N side), f16 operands
#define TM 128
#define TN 128
#define KC 64                            // f16 per K-chunk = 128 bytes/row
#define NCHUNK (D_DIM / KC)              // 16
#define CHUNK_MAT_BYTES (B_ROWS * 128)   // 524288 bytes per chunk-slab per matrix

#define A_TILE_BYTES (TM * 128)          // 16384
#define B_TILE_BYTES (TN * 128)          // 16384
#define STAGE_BYTES  (A_TILE_BYTES + B_TILE_BYTES)   // 32768
#define NSTAGE 3

// SMEM: [0..1024) control/reduction, then 3 stages of (A tile | B tile)
#define SMEM_TOTAL (1024 + NSTAGE * STAGE_BYTES)     // 99328  -> 2 CTAs/SM

#define N_CTAS ((B_ROWS / TM) * (B_ROWS / TN))       // 32 * 32 = 1024
#define CTA_THREADS 128                              // 4 warps, 2x2, tile 64x64

// ============================================================================
// Device scratch (static __device__ globals — no allocation allowed)
// f16, chunk-major, pre-swizzled (SW128): within each 512KB chunk slab,
//   byte offset = SWZ128(row*128 + kbyte). cp.async copies verbatim; smem
//   lands ldmatrix-ready with zero bank conflicts.
// ============================================================================
__device__ __align__(1024) __half g_zj[(size_t)B_ROWS * D_DIM];  // M side
__device__ __align__(1024) __half g_zi[(size_t)B_ROWS * D_DIM];  // N side
__device__ float g_partials[2 * N_CTAS];
__device__ unsigned g_done = 0;          // last-CTA ticket; reset by last CTA

// ============================================================================
// PTX helpers — base-target only (sm_80-class): cp.async, ldmatrix, mma.sync
// ============================================================================
__device__ __forceinline__ uint32_t smem_to_u32(const void* smem_ptr) {
    uint32_t addr;
    asm("{ .reg .u64 tmp; cvta.to.shared.u64 tmp, %1; cvt.u32.u64 %0, tmp; }"
        : "=r"(addr) : "l"(smem_ptr));
    return addr;
}

#define SWZ128(o) ((o) ^ (((o) >> 3) & 0x70))

__device__ __forceinline__ void cp_async16(uint32_t dst, const void* src) {
    asm volatile("cp.async.cg.shared.global [%0], [%1], 16;"
        :: "r"(dst), "l"(src) : "memory");
}
#define CP_COMMIT() asm volatile("cp.async.commit_group;" ::: "memory")
#define CP_WAIT(n)  asm volatile("cp.async.wait_group %0;" :: "n"(n) : "memory")

__device__ __forceinline__ void ldsm_x4(uint32_t* r, uint32_t addr) {
    asm volatile("ldmatrix.sync.aligned.m8n8.x4.shared.b16 {%0,%1,%2,%3}, [%4];"
        : "=r"(r[0]), "=r"(r[1]), "=r"(r[2]), "=r"(r[3]) : "r"(addr));
}

// f16 inputs, f16 accumulators (2 regs) — tests the f16-acc double-rate path.
__device__ __forceinline__ void mma16816_f16(uint32_t* d, const uint32_t* a,
                                             const uint32_t* b) {
    asm volatile(
        "mma.sync.aligned.m16n8k16.row.col.f16.f16.f16.f16 "
        "{%0,%1}, {%2,%3,%4,%5}, {%6,%7}, {%0,%1};"
        : "+r"(d[0]), "+r"(d[1])
        : "r"(a[0]), "r"(a[1]), "r"(a[2]), "r"(a[3]), "r"(b[0]), "r"(b[1]));
}

// ============================================================================
// Kernel 1: row L2-normalize fp32 -> f16 scratch (chunk-major, pre-swizzled)
// Warp-per-row, barrier-free, coalesced, two-pass (structure unchanged; only
// the output dtype switched bf16 -> f16, which also IMPROVES operand
// quantization: 5e-4 vs 4e-3 relative).
// 2048 blocks x 128 threads = 8192 warps = 8192 rows (2 matrices x 4096).
// ============================================================================
__global__ void __launch_bounds__(128) norm_f16_kernel(
    const float* __restrict__ emb_i, const float* __restrict__ emb_j) {
    int wid = threadIdx.x >> 5, lane = threadIdx.x & 31;
    int mat = blockIdx.x >> 10;                      // 0: emb_i, 1: emb_j
    int row = ((blockIdx.x & 1023) << 2) + wid;

    const float4* src = reinterpret_cast<const float4*>(mat ? emb_j : emb_i)
                        + (size_t)row * (D_DIM / 4);
    char* dstBase = reinterpret_cast<char*>(mat ? g_zj : g_zi);

    // Pass 1: sum of squares only (no payload kept live)
    float ss = 0.0f;
#pragma unroll
    for (int k = 0; k < 8; k++) {
        float4 t = src[lane + 32 * k];               // coalesced
        ss += t.x * t.x + t.y * t.y + t.z * t.z + t.w * t.w;
    }
#pragma unroll
    for (int o = 16; o > 0; o >>= 1) ss += __shfl_xor_sync(0xFFFFFFFFu, ss, o);
    float inv = 1.0f / fmaxf(sqrtf(ss), 1e-12f);

    // Pass 2: re-read (cache hit), scale, store
    uint32_t rowOff = (uint32_t)row * 128u + (uint32_t)(lane & 15) * 8u;
    uint32_t swOff = SWZ128(rowOff);
    int chunkBase = lane >> 4;                       // 0 or 1
#pragma unroll
    for (int k = 0; k < 8; k++) {
        float4 t = src[lane + 32 * k];
        __half2 lo = __floats2half2_rn(t.x * inv, t.y * inv);
        __half2 hi = __floats2half2_rn(t.z * inv, t.w * inv);
        uint2 pack;
        pack.x = *reinterpret_cast<uint32_t*>(&lo);
        pack.y = *reinterpret_cast<uint32_t*>(&hi);
        int chunk = 2 * k + chunkBase;               // 64-elem K-chunk
        *reinterpret_cast<uint2*>(
            dstBase + (size_t)chunk * CHUNK_MAT_BYTES + swOff) = pack;
    }
}

// ============================================================================
// Kernel 2: fused f16 mma.sync GEMM + softplus + reduce + last-CTA finalize
// grid (32, 32); 128 threads = 4 warps in 2x2, warp tile 64x64.
// f16 accumulators (64 regs, was 128) free registers for kk-level fragment
// DOUBLE-BUFFERING: ldsm for kk+1 issues before the MMA burst of kk, hiding
// the LDS latency that (with the f32-acc serial pattern) capped tensor at 62%.
// 3-stage cp.async pipeline, one __syncthreads per chunk; unconditional
// commit_group keeps wait_group counts exact through the tail. 2 CTAs/SM.
// ============================================================================
__device__ __forceinline__ void issue_loads(uint32_t dA, uint32_t dB,
                                            const char* srcA, const char* srcB,
                                            int tid) {
    // A tile 16384B = 1024 x 16B slices -> 8 per thread (128 threads)
#pragma unroll
    for (int i = 0; i < 8; i++) {
        uint32_t idx = (uint32_t)tid + 128u * i;
        cp_async16(dA + idx * 16u, srcA + (size_t)idx * 16u);
    }
    // B tile 16384B = 1024 x 16B slices -> 8 per thread
#pragma unroll
    for (int i = 0; i < 8; i++) {
        uint32_t idx = (uint32_t)tid + 128u * i;
        cp_async16(dB + idx * 16u, srcB + (size_t)idx * 16u);
    }
}

__global__ void __launch_bounds__(CTA_THREADS, 2) gemm_loss_kernel(float* __restrict__ out) {
    extern __shared__ __align__(1024) char smem[];
    uint32_t sb = smem_to_u32(smem);
    int tid = threadIdx.x;
    int wid = tid >> 5, lane = tid & 31;
    int wm = wid >> 1, wn = wid & 1;        // 2 x 2 warp grid, warp tile 64x64
    int tn = blockIdx.x, tm = blockIdx.y;

    uint32_t stA[NSTAGE], stB[NSTAGE];
#pragma unroll
    for (int s = 0; s < NSTAGE; s++) {
        stA[s] = sb + 1024 + s * STAGE_BYTES;
        stB[s] = stA[s] + A_TILE_BYTES;
    }

    const char* gA = reinterpret_cast<const char*>(g_zj) + (size_t)tm * TM * 128;
    const char* gB = reinterpret_cast<const char*>(g_zi) + (size_t)tn * TN * 128;

    // Prologue: chunks 0..NSTAGE-2 into stages 0..NSTAGE-2 (one group each)
#pragma unroll
    for (int c = 0; c < NSTAGE - 1; c++) {
        issue_loads(stA[c], stB[c], gA + (size_t)c * CHUNK_MAT_BYTES,
                    gB + (size_t)c * CHUNK_MAT_BYTES, tid);
        CP_COMMIT();
    }

    // Unswizzled ldmatrix byte offsets; swizzle applied per access so the
    // +kk*32 column advance happens BEFORE the XOR — no carry corruption.
    uint32_t aRow[4];
    {
        int r = lane & 15, hb = (lane >> 4) * 16;
#pragma unroll
        for (int i = 0; i < 4; i++)
            aRow[i] = (uint32_t)(wm * 64 + i * 16 + r) * 128u + hb;
    }
    uint32_t bRow[4];
    {
        int rn = (lane & 7) + ((lane >> 4) << 3);
        int bb = ((lane >> 3) & 1) * 16;
#pragma unroll
        for (int j2 = 0; j2 < 4; j2++)
            bRow[j2] = (uint32_t)(wn * 64 + j2 * 16 + rn) * 128u + bb;
    }

    uint32_t acc[64];                       // f16x2 accumulators (0 == f16 zero)
#pragma unroll
    for (int i = 0; i < 64; i++) acc[i] = 0u;

    int sIdx = 0;   // stage of chunk c (cycles 0,1,2,0,...)
    for (int c = 0; c < NCHUNK; c++) {
        CP_WAIT(NSTAGE - 2);   // chunk c's group retired (groups are exact)
        __syncthreads();       // chunk c visible; stage of chunk c-1 free

        int cn = c + NSTAGE - 1;
        int sNext = sIdx + (NSTAGE - 1);
        if (sNext >= NSTAGE) sNext -= NSTAGE;
        if (cn < NCHUNK)
            issue_loads(stA[sNext], stB[sNext],
                        gA + (size_t)cn * CHUNK_MAT_BYTES,
                        gB + (size_t)cn * CHUNK_MAT_BYTES, tid);
        CP_COMMIT();           // unconditional: tail groups may be empty

        uint32_t baseA = stA[sIdx], baseB = stB[sIdx];

        // kk-pipelined: fragments double-buffered; ldsm(kk+1) before MMA(kk)
        uint32_t af[2][4][4], bf[2][4][4];
#pragma unroll
        for (int i = 0; i < 4; i++)
            ldsm_x4(af[0][i], baseA + SWZ128(aRow[i] + 0u));
#pragma unroll
        for (int j2 = 0; j2 < 4; j2++)
            ldsm_x4(bf[0][j2], baseB + SWZ128(bRow[j2] + 0u));

#pragma unroll
        for (int kk = 0; kk < 4; kk++) {
            int cur = kk & 1, nxt = cur ^ 1;
            if (kk < 3) {
                uint32_t col = (uint32_t)(kk + 1) * 32u;
#pragma unroll
                for (int i = 0; i < 4; i++)
                    ldsm_x4(af[nxt][i], baseA + SWZ128(aRow[i] + col));
#pragma unroll
                for (int j2 = 0; j2 < 4; j2++)
                    ldsm_x4(bf[nxt][j2], baseB + SWZ128(bRow[j2] + col));
            }
#pragma unroll
            for (int i = 0; i < 4; i++)
#pragma unroll
                for (int j = 0; j < 8; j++)
                    mma16816_f16(&acc[(i * 8 + j) * 2], af[cur][i],
                                 &bf[cur][j >> 1][(j & 1) * 2]);
        }
        sIdx = (sIdx == NSTAGE - 1) ? 0 : sIdx + 1;
    }

    // ---- fused epilogue: softplus + diagonal split, all in registers ----
    // f16x2 acc layout per 16x8 tile: reg0 = row g, cols {tig*2, tig*2+1};
    //                                 reg1 = row g+8, same cols.
    int g = lane >> 2, tig = lane & 3;
    int rowBase = tm * TM + wm * 64;
    int colBase = tn * TN + wn * 64;
    float negs = 0.0f, poss = 0.0f;
#pragma unroll
    for (int i = 0; i < 4; i++) {
#pragma unroll
        for (int j = 0; j < 8; j++) {
            const uint32_t* d = &acc[(i * 8 + j) * 2];
#pragma unroll
            for (int h = 0; h < 2; h++) {
                __half2 hv = *reinterpret_cast<const __half2*>(&d[h]);
                float vlo = __low2float(hv), vhi = __high2float(hv);
                int row = rowBase + i * 16 + g + h * 8;
                int cl = colBase + j * 8 + tig * 2;
                if (row == cl) poss += __logf(1.0f + __expf(TEMP - vlo));
                else           negs += __logf(1.0f + __expf(vlo - TEMP));
                if (row == cl + 1) poss += __logf(1.0f + __expf(TEMP - vhi));
                else               negs += __logf(1.0f + __expf(vhi - TEMP));
            }
        }
    }
#pragma unroll
    for (int o = 16; o > 0; o >>= 1) {
        negs += __shfl_xor_sync(0xFFFFFFFFu, negs, o);
        poss += __shfl_xor_sync(0xFFFFFFFFu, poss, o);
    }
    float* red = reinterpret_cast<float*>(smem + 32);
    if (lane == 0) { red[wid] = negs; red[4 + wid] = poss; }
    __syncthreads();
    if (tid == 0) {
        float n = red[0] + red[1] + red[2] + red[3];
        float p = red[4] + red[5] + red[6] + red[7];
        int cta = tm * 32 + tn;
        g_partials[cta * 2]     = n;
        g_partials[cta * 2 + 1] = p;
    }

    // ---- last-CTA finalize (deterministic fixed-order double reduction) ----
    __shared__ unsigned isLast;
    __threadfence();                       // publish g_partials before ticket
    if (tid == 0) {
        unsigned v = atomicAdd(&g_done, 1u);
        isLast = (v == (unsigned)(N_CTAS - 1)) ? 1u : 0u;
    }
    __syncthreads();
    if (isLast) {
        __threadfence();                   // acquire: all partials visible
        double* sd = reinterpret_cast<double*>(smem + 1024);  // stage area free
        double n = 0.0, p = 0.0;
#pragma unroll
        for (int i = 0; i < N_CTAS / CTA_THREADS; i++) {   // fixed order: 8/thread
            int idx = tid + CTA_THREADS * i;
            n += (double)g_partials[idx * 2];
            p += (double)g_partials[idx * 2 + 1];
        }
        sd[tid] = n;
        sd[CTA_THREADS + tid] = p;
        __syncthreads();
        for (int o = CTA_THREADS / 2; o > 0; o >>= 1) {
            if (tid < o) {
                sd[tid] += sd[tid + o];
                sd[CTA_THREADS + tid] += sd[CTA_THREADS + tid + o];
            }
            __syncthreads();
        }
        if (tid == 0) {
            const double Bd = (double)B_ROWS;
            double loss = 0.5 * (sd[CTA_THREADS] / Bd)
                        + 0.5 * (sd[0] / (Bd * (Bd - 1.0)));
            out[0] = (float)loss;
            g_done = 0;                    // reset for next graph replay
        }
    }
}

// ============================================================================
// Launcher
// ============================================================================
extern "C" void kernel_launch(void* const* d_in, const int* in_sizes, int n_in,
                              void* d_out, int out_size) {
    (void)in_sizes; (void)n_in; (void)out_size;
    const float* emb_i = (const float*)d_in[0];
    const float* emb_j = (const float*)d_in[1];
    float* out = (float*)d_out;

    cudaFuncSetAttribute(gemm_loss_kernel,
                         cudaFuncAttributeMaxDynamicSharedMemorySize, SMEM_TOTAL);

    norm_f16_kernel<<<2048, 128>>>(emb_i, emb_j);
    dim3 grid(B_ROWS / TN, B_ROWS / TM);   // (32, 32)
    gemm_loss_kernel<<<grid, CTA_THREADS, SMEM_TOTAL>>>(out);
}

// round 17
// speedup vs baseline: 1.5499x; 1.5499x over previous
#include <cuda_runtime.h>
#include <cuda_bf16.h>
#include <cstdint>

// ============================================================================
// Problem constants
// ============================================================================
#define B_ROWS 4096
#define D_DIM  1024
#define TEMP   0.2f

// GEMM tiling: sim[4096,4096] = z_j (M side) @ z_i^T (N side), bf16 operands
#define TM 128
#define TN 128
#define KC 64                            // bf16 per K-chunk = 128 bytes/row
#define NCHUNK (D_DIM / KC)              // 16
#define CHUNK_MAT_BYTES (B_ROWS * 128)   // 524288 bytes per chunk-slab per matrix

#define A_TILE_BYTES (TM * 128)          // 16384
#define B_TILE_BYTES (TN * 128)          // 16384
#define STAGE_BYTES  (A_TILE_BYTES + B_TILE_BYTES)   // 32768
#define NSTAGE 3

// SMEM: [0..1024) control/reduction, then 3 stages of (A tile | B tile)
#define SMEM_TOTAL (1024 + NSTAGE * STAGE_BYTES)     // 99328  -> 2 CTAs/SM

#define N_TILES 1024                     // 32 x 32 tiles of 128x128
#define GRID_CTAS 304                    // 2 CTAs/SM x 152 SMs (GB300)
#define CTA_THREADS 128                  // 4 warps, 2x2, warp tile 64x64

// ============================================================================
// Device scratch (static __device__ globals — no allocation allowed)
// bf16, chunk-major, pre-swizzled (SW128): within each 512KB chunk slab,
//   byte offset = SWZ128(row*128 + kbyte). cp.async copies verbatim; smem
//   lands ldmatrix-ready with zero bank conflicts.
// ============================================================================
__device__ __align__(1024) __nv_bfloat16 g_zj[(size_t)B_ROWS * D_DIM];  // M side
__device__ __align__(1024) __nv_bfloat16 g_zi[(size_t)B_ROWS * D_DIM];  // N side
__device__ float g_partials[2 * GRID_CTAS];
__device__ unsigned g_done = 0;          // last-CTA ticket; reset by last CTA

// ============================================================================
// PTX helpers — base-target only (sm_80-class): cp.async, ldmatrix, mma.sync
// ============================================================================
__device__ __forceinline__ uint32_t smem_to_u32(const void* smem_ptr) {
    uint32_t addr;
    asm("{ .reg .u64 tmp; cvta.to.shared.u64 tmp, %1; cvt.u32.u64 %0, tmp; }"
        : "=r"(addr) : "l"(smem_ptr));
    return addr;
}

#define SWZ128(o) ((o) ^ (((o) >> 3) & 0x70))

__device__ __forceinline__ void cp_async16(uint32_t dst, const void* src) {
    asm volatile("cp.async.cg.shared.global [%0], [%1], 16;"
        :: "r"(dst), "l"(src) : "memory");
}
#define CP_COMMIT() asm volatile("cp.async.commit_group;" ::: "memory")
#define CP_WAIT(n)  asm volatile("cp.async.wait_group %0;" :: "n"(n) : "memory")

__device__ __forceinline__ void ldsm_x4(uint32_t* r, uint32_t addr) {
    asm volatile("ldmatrix.sync.aligned.m8n8.x4.shared.b16 {%0,%1,%2,%3}, [%4];"
        : "=r"(r[0]), "=r"(r[1]), "=r"(r[2]), "=r"(r[3]) : "r"(addr));
}

__device__ __forceinline__ void mma16816(float* d, const uint32_t* a, const uint32_t* b) {
    asm volatile(
        "mma.sync.aligned.m16n8k16.row.col.f32.bf16.bf16.f32 "
        "{%0,%1,%2,%3}, {%4,%5,%6,%7}, {%8,%9}, {%0,%1,%2,%3};"
        : "+f"(d[0]), "+f"(d[1]), "+f"(d[2]), "+f"(d[3])
        : "r"(a[0]), "r"(a[1]), "r"(a[2]), "r"(a[3]), "r"(b[0]), "r"(b[1]));
}

// ============================================================================
// Kernel 1: row L2-normalize fp32 -> bf16 scratch (chunk-major, pre-swizzled)
// Warp-per-row, barrier-free, coalesced, two-pass (UNCHANGED from R14/R15).
// 2048 blocks x 128 threads = 8192 warps = 8192 rows (2 matrices x 4096).
// ============================================================================
__global__ void __launch_bounds__(128) norm_bf16_kernel(
    const float* __restrict__ emb_i, const float* __restrict__ emb_j) {
    int wid = threadIdx.x >> 5, lane = threadIdx.x & 31;
    int mat = blockIdx.x >> 10;                      // 0: emb_i, 1: emb_j
    int row = ((blockIdx.x & 1023) << 2) + wid;

    const float4* src = reinterpret_cast<const float4*>(mat ? emb_j : emb_i)
                        + (size_t)row * (D_DIM / 4);
    char* dstBase = reinterpret_cast<char*>(mat ? g_zj : g_zi);

    float ss = 0.0f;
#pragma unroll
    for (int k = 0; k < 8; k++) {
        float4 t = src[lane + 32 * k];               // coalesced
        ss += t.x * t.x + t.y * t.y + t.z * t.z + t.w * t.w;
    }
#pragma unroll
    for (int o = 16; o > 0; o >>= 1) ss += __shfl_xor_sync(0xFFFFFFFFu, ss, o);
    float inv = 1.0f / fmaxf(sqrtf(ss), 1e-12f);

    uint32_t rowOff = (uint32_t)row * 128u + (uint32_t)(lane & 15) * 8u;
    uint32_t swOff = SWZ128(rowOff);
    int chunkBase = lane >> 4;                       // 0 or 1
#pragma unroll
    for (int k = 0; k < 8; k++) {
        float4 t = src[lane + 32 * k];
        __nv_bfloat162 lo = __floats2bfloat162_rn(t.x * inv, t.y * inv);
        __nv_bfloat162 hi = __floats2bfloat162_rn(t.z * inv, t.w * inv);
        uint2 pack;
        pack.x = *reinterpret_cast<uint32_t*>(&lo);
        pack.y = *reinterpret_cast<uint32_t*>(&hi);
        int chunk = 2 * k + chunkBase;               // 64-elem K-chunk
        *reinterpret_cast<uint2*>(
            dstBase + (size_t)chunk * CHUNK_MAT_BYTES + swOff) = pack;
    }
}

// ============================================================================
// Kernel 2: PERSISTENT fused bf16 GEMM + softplus + reduce + last-CTA finalize
// grid = 304 persistent CTAs (2/SM); each processes tiles bid, bid+304, ...
// (CTAs 0..111 get 4 tiles, 112..303 get 3). The chunk pipeline is FLATTENED
// across tiles: global counter q over myTiles*16 chunks, so tile t+1's first
// chunks prefetch during tile t's last chunks, and the per-tile epilogue
// (barrier-free: per-thread running totals) overlaps in-flight loads.
// Mainloop body (wait/sync/issue/commit + 64x64 warp-tile MMA) is byte-
// identical to R15. bf16 operands, f32 accumulators (fastest mode measured).
// ============================================================================
__device__ __forceinline__ void issue_loads(uint32_t dA, uint32_t dB,
                                            const char* srcA, const char* srcB,
                                            int tid) {
#pragma unroll
    for (int i = 0; i < 8; i++) {
        uint32_t idx = (uint32_t)tid + 128u * i;
        cp_async16(dA + idx * 16u, srcA + (size_t)idx * 16u);
    }
#pragma unroll
    for (int i = 0; i < 8; i++) {
        uint32_t idx = (uint32_t)tid + 128u * i;
        cp_async16(dB + idx * 16u, srcB + (size_t)idx * 16u);
    }
}

// global chunk q (within this CTA's flattened stream) -> gmem slab pointers
__device__ __forceinline__ void chunk_src(int bid, int q,
                                          const char** srcA, const char** srcB) {
    int tile = bid + GRID_CTAS * (q >> 4);
    int c = q & 15;
    int tm = tile >> 5, tn = tile & 31;
    *srcA = reinterpret_cast<const char*>(g_zj)
            + (size_t)c * CHUNK_MAT_BYTES + (size_t)tm * TM * 128;
    *srcB = reinterpret_cast<const char*>(g_zi)
            + (size_t)c * CHUNK_MAT_BYTES + (size_t)tn * TN * 128;
}

__global__ void __launch_bounds__(CTA_THREADS, 2) gemm_loss_kernel(float* __restrict__ out) {
    extern __shared__ __align__(1024) char smem[];
    uint32_t sb = smem_to_u32(smem);
    int tid = threadIdx.x;
    int wid = tid >> 5, lane = tid & 31;
    int wm = wid >> 1, wn = wid & 1;        // 2 x 2 warp grid, warp tile 64x64
    int bid = blockIdx.x;

    uint32_t stA[NSTAGE], stB[NSTAGE];
#pragma unroll
    for (int s = 0; s < NSTAGE; s++) {
        stA[s] = sb + 1024 + s * STAGE_BYTES;
        stB[s] = stA[s] + A_TILE_BYTES;
    }

    int myTiles = (bid < (N_TILES - 3 * GRID_CTAS)) ? 4 : 3;   // 112 CTAs get 4
    int totalQ = myTiles * NCHUNK;

    // Prologue: flattened chunks 0,1 into stages 0,1
#pragma unroll
    for (int q = 0; q < NSTAGE - 1; q++) {
        const char *sA, *sBp;
        chunk_src(bid, q, &sA, &sBp);
        issue_loads(stA[q], stB[q], sA, sBp, tid);
        CP_COMMIT();
    }

    // Unswizzled ldmatrix byte offsets; swizzle applied per access so the
    // +kk*32 column advance happens BEFORE the XOR — no carry corruption.
    uint32_t aRow[4];
    {
        int r = lane & 15, hb = (lane >> 4) * 16;
#pragma unroll
        for (int i = 0; i < 4; i++)
            aRow[i] = (uint32_t)(wm * 64 + i * 16 + r) * 128u + hb;
    }
    uint32_t bRow[4];
    {
        int rn = (lane & 7) + ((lane >> 4) << 3);
        int bb = ((lane >> 3) & 1) * 16;
#pragma unroll
        for (int j2 = 0; j2 < 4; j2++)
            bRow[j2] = (uint32_t)(wn * 64 + j2 * 16 + rn) * 128u + bb;
    }

    float acc[128];
#pragma unroll
    for (int i = 0; i < 128; i++) acc[i] = 0.0f;

    int g = lane >> 2, tig = lane & 3;
    float negsTot = 0.0f, possTot = 0.0f;   // per-thread running totals

    int sIdx = 0;   // stage of flattened chunk q (cycles 0,1,2,...)
    for (int q = 0; q < totalQ; q++) {
        CP_WAIT(NSTAGE - 2);   // chunk q's group retired (groups are exact)
        __syncthreads();       // chunk q visible; stage of chunk q-1 free

        int qn = q + NSTAGE - 1;
        int sNext = sIdx + (NSTAGE - 1);
        if (sNext >= NSTAGE) sNext -= NSTAGE;
        if (qn < totalQ) {
            const char *sA, *sBp;
            chunk_src(bid, qn, &sA, &sBp);
            issue_loads(stA[sNext], stB[sNext], sA, sBp, tid);
        }
        CP_COMMIT();           // unconditional: tail groups may be empty

        uint32_t baseA = stA[sIdx], baseB = stB[sIdx];
#pragma unroll
        for (int kk = 0; kk < 4; kk++) {
            uint32_t af[4][4], bf[4][4];
#pragma unroll
            for (int i = 0; i < 4; i++)
                ldsm_x4(af[i], baseA + SWZ128(aRow[i] + kk * 32u));
#pragma unroll
            for (int j2 = 0; j2 < 4; j2++)
                ldsm_x4(bf[j2], baseB + SWZ128(bRow[j2] + kk * 32u));
#pragma unroll
            for (int i = 0; i < 4; i++)
#pragma unroll
                for (int j = 0; j < 8; j++)
                    mma16816(&acc[(i * 8 + j) * 4], af[i], &bf[j >> 1][(j & 1) * 2]);
        }
        sIdx = (sIdx == NSTAGE - 1) ? 0 : sIdx + 1;

        // ---- per-tile epilogue: barrier-free softplus into running totals;
        //      overlaps the already-issued loads of the next tile's chunks ----
        if ((q & 15) == 15) {
            int tile = bid + GRID_CTAS * (q >> 4);
            int rowBase = (tile >> 5) * TM + wm * 64;
            int colBase = (tile & 31) * TN + wn * 64;
#pragma unroll
            for (int i = 0; i < 4; i++) {
#pragma unroll
                for (int j = 0; j < 8; j++) {
                    float* d = &acc[(i * 8 + j) * 4];
#pragma unroll
                    for (int r = 0; r < 4; r++) {
                        int row = rowBase + i * 16 + g + (r >> 1) * 8;
                        int col = colBase + j * 8 + tig * 2 + (r & 1);
                        float v = d[r];
                        if (row == col)
                            possTot += __logf(1.0f + __expf(TEMP - v));
                        else
                            negsTot += __logf(1.0f + __expf(v - TEMP));
                        d[r] = 0.0f;              // reset for next tile
                    }
                }
            }
        }
    }

    // ---- one block reduction at the very end ----
#pragma unroll
    for (int o = 16; o > 0; o >>= 1) {
        negsTot += __shfl_xor_sync(0xFFFFFFFFu, negsTot, o);
        possTot += __shfl_xor_sync(0xFFFFFFFFu, possTot, o);
    }
    float* red = reinterpret_cast<float*>(smem + 32);
    if (lane == 0) { red[wid] = negsTot; red[4 + wid] = possTot; }
    __syncthreads();
    if (tid == 0) {
        float n = red[0] + red[1] + red[2] + red[3];
        float p = red[4] + red[5] + red[6] + red[7];
        g_partials[bid * 2]     = n;
        g_partials[bid * 2 + 1] = p;
    }

    // ---- last-CTA finalize (deterministic fixed-order double reduction) ----
    __shared__ unsigned isLast;
    __threadfence();                       // publish g_partials before ticket
    if (tid == 0) {
        unsigned v = atomicAdd(&g_done, 1u);
        isLast = (v == (unsigned)(GRID_CTAS - 1)) ? 1u : 0u;
    }
    __syncthreads();
    if (isLast) {
        __threadfence();                   // acquire: all partials visible
        double* sd = reinterpret_cast<double*>(smem + 1024);  // stage area free
        double n = 0.0, p = 0.0;
#pragma unroll
        for (int i = 0; i < 3; i++) {      // fixed order; 304 = 2*128 + 48
            int idx = tid + CTA_THREADS * i;
            if (idx < GRID_CTAS) {
                n += (double)g_partials[idx * 2];
                p += (double)g_partials[idx * 2 + 1];
            }
        }
        sd[tid] = n;
        sd[CTA_THREADS + tid] = p;
        __syncthreads();
        for (int o = CTA_THREADS / 2; o > 0; o >>= 1) {
            if (tid < o) {
                sd[tid] += sd[tid + o];
                sd[CTA_THREADS + tid] += sd[CTA_THREADS + tid + o];
            }
            __syncthreads();
        }
        if (tid == 0) {
            const double Bd = (double)B_ROWS;
            double loss = 0.5 * (sd[CTA_THREADS] / Bd)
                        + 0.5 * (sd[0] / (Bd * (Bd - 1.0)));
            out[0] = (float)loss;
            g_done = 0;                    // reset for next graph replay
        }
    }
}

// ============================================================================
// Launcher
// ============================================================================
extern "C" void kernel_launch(void* const* d_in, const int* in_sizes, int n_in,
                              void* d_out, int out_size) {
    (void)in_sizes; (void)n_in; (void)out_size;
    const float* emb_i = (const float*)d_in[0];
    const float* emb_j = (const float*)d_in[1];
    float* out = (float*)d_out;

    cudaFuncSetAttribute(gemm_loss_kernel,
                         cudaFuncAttributeMaxDynamicSharedMemorySize, SMEM_TOTAL);

    norm_bf16_kernel<<<2048, 128>>>(emb_i, emb_j);
    gemm_loss_kernel<<<GRID_CTAS, CTA_THREADS, SMEM_TOTAL>>>(out);
}